// round 5
// baseline (speedup 1.0000x reference)
#include <cuda_runtime.h>
#include <cstdint>

typedef unsigned long long ULL;
typedef uint32_t U32;

#define C_DIMM 256
#define L_DIMM 2048
#define K_CB   8192
#define M_DIM  16384
#define EMB_N  4194304

// smem layout (float offsets)
#define A_STR  260
#define B_STR  36
#define OFF_B   (128 * A_STR)                 // 33280
#define OFF_CSQ (OFF_B + 2 * 128 * B_STR)     // 42496
#define OFF_KH  (OFF_CSQ + 8192)              // 50688 (8B-aligned in bytes)
#define OFF_XN  (OFF_KH + 1024)               // 51712
#define SMEM_FLOATS (OFF_XN + 128)            // 51840
#define SMEM_BYTES  (SMEM_FLOATS * 4)         // 207360

__device__ float g_csq[K_CB];
__device__ float g_cmax[1];
__device__ int   g_flag[M_DIM];
__device__ int   g_ncand[M_DIM];
__device__ int   g_cand[M_DIM * 4];
__device__ int   g_code[M_DIM];
__device__ float g_partial[EMB_N / 256];

// ---------------- helpers ----------------
__device__ __forceinline__ float rna(float v) {
    U32 r; asm("cvt.rna.tf32.f32 %0, %1;" : "=r"(r) : "f"(v));
    return __uint_as_float(r);
}
__device__ __forceinline__ float4 rna4(float4 v) {
    v.x = rna(v.x); v.y = rna(v.y); v.z = rna(v.z); v.w = rna(v.w); return v;
}
__device__ __forceinline__ ULL makeKey(float s, int gk) {
    unsigned u = __float_as_uint(s);
    u = (u & 0x80000000u) ? ~u : (u | 0x80000000u);
    return ((ULL)u << 32) | (unsigned)(0xFFFFFFFFu - (unsigned)gk);
}
__device__ __forceinline__ float keyVal(ULL k) {
    unsigned v = (unsigned)(k >> 32);
    v = (v & 0x80000000u) ? (v ^ 0x80000000u) : ~v;
    return __uint_as_float(v);
}
__device__ __forceinline__ int keyIdx(ULL k) {
    return (int)(0xFFFFFFFFu - (unsigned)(k & 0xffffffffu));
}
__device__ __forceinline__ ULL maxk(ULL a, ULL b) { return a > b ? a : b; }

__device__ __forceinline__ void ins4(ULL* t, ULL k) {
    if (k > t[3]) {
        t[3] = k;
        if (t[3] > t[2]) { ULL z = t[2]; t[2] = t[3]; t[3] = z;
            if (t[2] > t[1]) { z = t[1]; t[1] = t[2]; t[2] = z;
                if (t[1] > t[0]) { z = t[0]; t[0] = t[1]; t[1] = z; } } }
    }
}

// legacy tensor-core mma (sm_80 PTX -> HMMA on Blackwell; no sm_100a features)
__device__ __forceinline__ void mma8(float* c, const U32* a, U32 b0, U32 b1) {
    asm volatile(
        "mma.sync.aligned.m16n8k8.row.col.f32.tf32.tf32.f32 "
        "{%0,%1,%2,%3}, {%4,%5,%6,%7}, {%8,%9}, {%0,%1,%2,%3};"
        : "+f"(c[0]), "+f"(c[1]), "+f"(c[2]), "+f"(c[3])
        : "r"(a[0]), "r"(a[1]), "r"(a[2]), "r"(a[3]), "r"(b0), "r"(b1));
}

// ---------------- kernel 1: codebook squared norms ----------------
__global__ void csq_kernel(const float* __restrict__ cb) {
    int k = blockIdx.x * 8 + (threadIdx.x >> 5);
    int lane = threadIdx.x & 31;
    const float* row = cb + (size_t)k * C_DIMM;
    float s = 0.0f;
    #pragma unroll
    for (int c = lane; c < C_DIMM; c += 32) { float v = row[c]; s = fmaf(v, v, s); }
    #pragma unroll
    for (int o = 16; o > 0; o >>= 1) s += __shfl_xor_sync(0xffffffffu, s, o);
    if (lane == 0) g_csq[k] = s;
}

// ---------------- kernel 2: max codebook norm ----------------
__global__ void cmax_kernel() {
    __shared__ float sr[256];
    float m = 0.0f;
    for (int i = threadIdx.x; i < K_CB; i += 256) m = fmaxf(m, g_csq[i]);
    sr[threadIdx.x] = m;
    __syncthreads();
    #pragma unroll
    for (int o = 128; o > 0; o >>= 1) {
        if (threadIdx.x < o) sr[threadIdx.x] = fmaxf(sr[threadIdx.x], sr[threadIdx.x + o]);
        __syncthreads();
    }
    if (threadIdx.x == 0) g_cmax[0] = sqrtf(sr[0]);
}

// ---------------- kernel 3: mma.sync tf32 GEMM + guaranteed argmax -----------
__global__ __launch_bounds__(256, 1) void argmax_tc(const float* __restrict__ x,
                                                    const float* __restrict__ cb) {
    extern __shared__ float sm[];
    float* As   = sm;                       // [128][A_STR]
    float* Bs   = sm + OFF_B;               // [2][128][B_STR]
    float* csqS = sm + OFF_CSQ;             // [8192]
    ULL*   kh   = (ULL*)(sm + OFF_KH);      // [128][4]
    float* xns  = sm + OFF_XN;              // [128]

    const int tid = threadIdx.x;
    const int w = tid >> 5, lane = tid & 31;
    const int g = lane >> 2, t = lane & 3;
    const int mwarp = w >> 1, nwarp = w & 1;

    const int rowBase = blockIdx.x * 128;
    const int bidx = rowBase >> 11, l0 = rowBase & 2047;
    const float* xb = x + (size_t)bidx * (C_DIMM * L_DIMM) + l0;

    // stage csq (fp32 exact)
    for (int i = tid; i < K_CB; i += 256) csqS[i] = g_csq[i];

    // stage A: As[m][c] tf32-rounded; loads coalesced along l
    for (int i = tid; i < 8192; i += 256) {
        int c = i >> 5, m4 = i & 31;
        float4 v = rna4(*(const float4*)(xb + (size_t)c * L_DIMM + m4 * 4));
        int m = m4 * 4;
        As[(m + 0) * A_STR + c] = v.x;
        As[(m + 1) * A_STR + c] = v.y;
        As[(m + 2) * A_STR + c] = v.z;
        As[(m + 3) * A_STR + c] = v.w;
    }

    // stage B chunk 0 into buf 0
    const int ldn = tid >> 1, ldk = (tid & 1) * 4;
    {
        const float* src = cb + (size_t)ldn * C_DIMM + ldk * 4;
        #pragma unroll
        for (int j = 0; j < 4; ++j) {
            float4 v = rna4(*(const float4*)(src + j * 4));
            *(float4*)&Bs[ldn * B_STR + (ldk + j) * 4] = v;
        }
    }
    __syncthreads();

    // per-row norms (from rna'd A; slack in margin covers the rounding)
    if (tid < 128) {
        float s = 0.0f;
        const float* ar = As + tid * A_STR;
        #pragma unroll 8
        for (int c = 0; c < C_DIMM; ++c) { float v = ar[c]; s = fmaf(v, v, s); }
        xns[tid] = sqrtf(s);
    }

    float acc[2][8][4];
    ULL top[4][4];
    #pragma unroll
    for (int s = 0; s < 4; ++s)
        #pragma unroll
        for (int j = 0; j < 4; ++j) top[s][j] = 0ULL;

    const float* Ab = As + (size_t)(mwarp * 32 + g) * A_STR + t;
    const float* Bw = Bs + (size_t)(nwarp * 64 + g) * B_STR + t;

    for (int gc = 0; gc < 512; ++gc) {       // 64 codebook tiles x 8 k-chunks
        const int kt = gc >> 3, ch = gc & 7, buf = gc & 1;

        float4 nx[4];
        const bool more = (gc + 1 < 512);
        if (more) {
            const int nkt = (gc + 1) >> 3, nch = (gc + 1) & 7;
            const float* src = cb + (size_t)(nkt * 128 + ldn) * C_DIMM + nch * 32 + ldk * 4;
            #pragma unroll
            for (int j = 0; j < 4; ++j) nx[j] = *(const float4*)(src + j * 4);
        }
        if (ch == 0) {
            #pragma unroll
            for (int mt = 0; mt < 2; ++mt)
                #pragma unroll
                for (int nt = 0; nt < 8; ++nt)
                    #pragma unroll
                    for (int j = 0; j < 4; ++j) acc[mt][nt][j] = 0.0f;
        }

        // compute chunk gc from Bs[buf]
        const float* Bb = Bw + buf * (128 * B_STR);
        #pragma unroll
        for (int ks = 0; ks < 4; ++ks) {
            const int kA = ch * 32 + ks * 8;
            U32 af[2][4];
            #pragma unroll
            for (int mt = 0; mt < 2; ++mt) {
                af[mt][0] = __float_as_uint(Ab[(mt * 16) * A_STR + kA]);
                af[mt][1] = __float_as_uint(Ab[(mt * 16 + 8) * A_STR + kA]);
                af[mt][2] = __float_as_uint(Ab[(mt * 16) * A_STR + kA + 4]);
                af[mt][3] = __float_as_uint(Ab[(mt * 16 + 8) * A_STR + kA + 4]);
            }
            #pragma unroll
            for (int nt = 0; nt < 8; ++nt) {
                U32 b0 = __float_as_uint(Bb[nt * 8 * B_STR + ks * 8]);
                U32 b1 = __float_as_uint(Bb[nt * 8 * B_STR + ks * 8 + 4]);
                mma8(acc[0][nt], af[0], b0, b1);
                mma8(acc[1][nt], af[1], b0, b1);
            }
        }

        if (more) {
            #pragma unroll
            for (int j = 0; j < 4; ++j) {
                float4 v = rna4(nx[j]);
                *(float4*)&Bs[(buf ^ 1) * (128 * B_STR) + ldn * B_STR + (ldk + j) * 4] = v;
            }
        }
        __syncthreads();

        if (ch == 7) {  // fold this tile's 64 scores into per-lane true top-4
            const int cb0 = kt * 128 + nwarp * 64 + 2 * t;
            #pragma unroll
            for (int nt = 0; nt < 8; ++nt) {
                int colg = cb0 + nt * 8;
                float2 cq = *(const float2*)&csqS[colg];
                #pragma unroll
                for (int mt = 0; mt < 2; ++mt) {
                    float s0 = fmaf(-2.0f, acc[mt][nt][0], cq.x);
                    float s1 = fmaf(-2.0f, acc[mt][nt][1], cq.y);
                    float s2 = fmaf(-2.0f, acc[mt][nt][2], cq.x);
                    float s3 = fmaf(-2.0f, acc[mt][nt][3], cq.y);
                    ins4(top[mt * 2],     makeKey(s0, colg));
                    ins4(top[mt * 2],     makeKey(s1, colg + 1));
                    ins4(top[mt * 2 + 1], makeKey(s2, colg));
                    ins4(top[mt * 2 + 1], makeKey(s3, colg + 1));
                }
            }
        }
    }

    // merge across the 4 lanes of each quad (they share rows)
    #pragma unroll
    for (int off = 1; off <= 2; off <<= 1) {
        #pragma unroll
        for (int s = 0; s < 4; ++s) {
            ULL o0 = __shfl_xor_sync(0xffffffffu, top[s][0], off);
            ULL o1 = __shfl_xor_sync(0xffffffffu, top[s][1], off);
            ULL o2 = __shfl_xor_sync(0xffffffffu, top[s][2], off);
            ULL o3 = __shfl_xor_sync(0xffffffffu, top[s][3], off);
            ins4(top[s], o0); ins4(top[s], o1); ins4(top[s], o2); ins4(top[s], o3);
        }
    }
    // cross n-warp merge via smem
    if (nwarp == 1 && t == 0) {
        #pragma unroll
        for (int s = 0; s < 4; ++s) {
            int r = mwarp * 32 + (s >> 1) * 16 + (s & 1) * 8 + g;
            #pragma unroll
            for (int j = 0; j < 4; ++j) kh[r * 4 + j] = top[s][j];
        }
    }
    __syncthreads();
    if (nwarp == 0 && t == 0) {
        float cm = g_cmax[0];
        #pragma unroll
        for (int s = 0; s < 4; ++s) {
            int r = mwarp * 32 + (s >> 1) * 16 + (s & 1) * 8 + g;
            #pragma unroll
            for (int j = 0; j < 4; ++j) ins4(top[s], kh[r * 4 + j]);
            float marg = xns[r] * cm * (1.0f / 256.0f) + 0.05f;  // rigorous 2E + slack
            float v1 = keyVal(top[s][0]), v2 = keyVal(top[s][1]);
            float v3 = keyVal(top[s][2]), v4 = keyVal(top[s][3]);
            int row = rowBase + r;
            int c0 = keyIdx(top[s][0]);
            g_code[row] = c0;
            if (v1 - v4 <= marg) {
                g_flag[row] = 2;                     // rare: full exact rescan
            } else if (v1 - v2 > marg) {
                g_flag[row] = 0;                     // provably exact
            } else {
                int nc = 2;
                g_cand[row * 4 + 0] = c0;
                g_cand[row * 4 + 1] = keyIdx(top[s][1]);
                if (v1 - v3 <= marg) { g_cand[row * 4 + 2] = keyIdx(top[s][2]); nc = 3; }
                g_flag[row] = 1;
                g_ncand[row] = nc;
            }
        }
    }
}

// ---------------- kernel 4: exact-fp32 rescue for flagged rows ----------------
__global__ void rescue_kernel(const float* __restrict__ x, const float* __restrict__ cb) {
    __shared__ float xs[8][C_DIMM];
    int w = threadIdx.x >> 5, lane = threadIdx.x & 31;
    int row = blockIdx.x * 8 + w;
    int fl = g_flag[row];
    if (fl == 0) return;
    int b = row >> 11, l = row & 2047;
    const float* xr = x + (size_t)b * C_DIMM * L_DIMM + l;
    #pragma unroll
    for (int i = 0; i < 8; ++i) xs[w][lane + 32 * i] = xr[(size_t)(lane + 32 * i) * L_DIMM];
    __syncwarp();
    const float4* x4 = (const float4*)xs[w];
    ULL best = 0ULL;
    if (fl == 1) {
        int nc = g_ncand[row];
        if (lane < nc) {
            int k = g_cand[row * 4 + lane];
            const float4* cr = (const float4*)(cb + (size_t)k * C_DIMM);
            float d = 0.0f;
            #pragma unroll 8
            for (int i = 0; i < 64; ++i) {
                float4 a = x4[i], c = cr[i];
                d = fmaf(a.x, c.x, d); d = fmaf(a.y, c.y, d);
                d = fmaf(a.z, c.z, d); d = fmaf(a.w, c.w, d);
            }
            best = makeKey(fmaf(-2.0f, d, g_csq[k]), k);
        }
    } else {
        for (int k = lane; k < K_CB; k += 32) {
            const float4* cr = (const float4*)(cb + (size_t)k * C_DIMM);
            float d = 0.0f;
            #pragma unroll 8
            for (int i = 0; i < 64; ++i) {
                float4 a = x4[i], c = cr[i];
                d = fmaf(a.x, c.x, d); d = fmaf(a.y, c.y, d);
                d = fmaf(a.z, c.z, d); d = fmaf(a.w, c.w, d);
            }
            best = maxk(best, makeKey(fmaf(-2.0f, d, g_csq[k]), k));
        }
    }
    #pragma unroll
    for (int o = 16; o > 0; o >>= 1)
        best = maxk(best, __shfl_xor_sync(0xffffffffu, best, o));
    if (lane == 0) g_code[row] = keyIdx(best);
}

// ---------------- output kernels ----------------
__global__ void code_cast_kernel(float* __restrict__ out_code) {
    int i = blockIdx.x * 256 + threadIdx.x;
    if (i < M_DIM) out_code[i] = (float)g_code[i];
}

__global__ void gather_loss_kernel(const float* __restrict__ x,
                                   const float* __restrict__ cb,
                                   float* __restrict__ emb_out) {
    __shared__ float sred[256];
    int idx = blockIdx.x * 256 + threadIdx.x;
    int bb = idx >> 19;
    int rem = idx & ((1 << 19) - 1);
    int c = rem >> 11;
    int l = rem & (L_DIMM - 1);
    int code = g_code[bb * L_DIMM + l];
    float v = __ldg(&cb[(size_t)code * C_DIMM + c]);
    emb_out[idx] = v;
    float d = x[idx] - v;
    sred[threadIdx.x] = d * d;
    __syncthreads();
    #pragma unroll
    for (int o = 128; o > 0; o >>= 1) {
        if (threadIdx.x < o) sred[threadIdx.x] += sred[threadIdx.x + o];
        __syncthreads();
    }
    if (threadIdx.x == 0) g_partial[blockIdx.x] = sred[0];
}

__global__ void finalize_kernel(float* __restrict__ loss_out) {
    __shared__ float sred[256];
    float s = 0.0f;
    for (int i = threadIdx.x; i < EMB_N / 256; i += 256) s += g_partial[i];
    sred[threadIdx.x] = s;
    __syncthreads();
    #pragma unroll
    for (int o = 128; o > 0; o >>= 1) {
        if (threadIdx.x < o) sred[threadIdx.x] += sred[threadIdx.x + o];
        __syncthreads();
    }
    if (threadIdx.x == 0) loss_out[0] = sred[0] * (1.0f / (float)EMB_N);
}

// ---------------- launch ----------------
extern "C" void kernel_launch(void* const* d_in, const int* in_sizes, int n_in,
                              void* d_out, int out_size) {
    const float* x  = (const float*)d_in[0];   // (8, 256, 2048)
    const float* cb = (const float*)d_in[1];   // (8192, 256)
    float* out = (float*)d_out;

    cudaFuncSetAttribute(argmax_tc, cudaFuncAttributeMaxDynamicSharedMemorySize, SMEM_BYTES);

    csq_kernel<<<K_CB / 8, 256>>>(cb);
    cmax_kernel<<<1, 256>>>();
    argmax_tc<<<M_DIM / 128, 256, SMEM_BYTES>>>(x, cb);
    rescue_kernel<<<M_DIM / 8, 256>>>(x, cb);

    const int full = M_DIM + EMB_N + 1;
    if (out_size >= full) {
        code_cast_kernel<<<(M_DIM + 255) / 256, 256>>>(out);
        gather_loss_kernel<<<EMB_N / 256, 256>>>(x, cb, out + M_DIM);
        finalize_kernel<<<1, 256>>>(out + M_DIM + EMB_N);
    } else if (out_size == EMB_N) {
        gather_loss_kernel<<<EMB_N / 256, 256>>>(x, cb, out);
    } else if (out_size == M_DIM) {
        code_cast_kernel<<<(M_DIM + 255) / 256, 256>>>(out);
    } else {
        gather_loss_kernel<<<EMB_N / 256, 256>>>(x, cb, out);
    }
}